// round 9
// baseline (speedup 1.0000x reference)
#include <cuda_runtime.h>
#include <math.h>

// Problem constants
#define BB 4
#define HH 200
#define WW 176
#define HW (HH*WW)         // 35200
#define FA 10
#define NF 5
#define NFR (BB*NF)        // 20 (b,frame) pairs
#define NPF (HW*2)         // 70400 elements per frame
#define NPOS (BB*HW)       // 140800 positions = 550*256 exactly
#define EPSV 1e-6f
#define NBIN 4096
#define CAP 4096
#define SBLK 69            // blocks per frame in k_sumfin (NPF/4 = 17600 = 69*256 - ...)

// ---- scratch (device globals; zero-initialized at load; self-cleaning) ----
__device__ float  g_vbuf[BB*NF*NPF];   // masked psm logits, 5.6MB
__device__ int    g_hist[NFR*NBIN];    // 12-bit-prefix histograms
__device__ int    g_pcnt[NFR];
__device__ float  g_cbuf[NFR*CAP];     // threshold-bin candidates
__device__ int    g_ccount[NFR];
__device__ int    g_fdone[NFR];        // per-frame arrival counters
__device__ double g_clspos, g_huber, g_num;
__device__ int    g_fin_done;

// monotonic float<->uint key mapping (ascending)
__device__ __forceinline__ unsigned kmap(float x){
    unsigned u = __float_as_uint(x);
    return (u & 0x80000000u) ? ~u : (u | 0x80000000u);
}
__device__ __forceinline__ float kunmap(unsigned m){
    unsigned u = (m & 0x80000000u) ? (m & 0x7FFFFFFFu) : ~m;
    return __uint_as_float(u);
}
// neg-class loss from raw logit (monotone non-decreasing in x => top-k by x == top-k by v)
__device__ __forceinline__ float vneg(float x){
    float pp = 1.0f/(1.0f + expf(-x));
    return -logf(1.0f - pp + EPSV);
}
__device__ __forceinline__ double wredd(double v){
    #pragma unroll
    for (int o=16;o;o>>=1) v += __shfl_down_sync(0xffffffffu, v, o);
    return v;
}

// hierarchical suffix scan over shared hist[NBIN], 256 threads.
// thread 0 writes (*oP,*oR); all threads sync'd on exit.
__device__ __forceinline__ void scan_pick256(int* hist, int* Sc, int* Sw,
                                             int k, int* oP, int* oR, int tid)
{
    const int C = NBIN/256;      // 16
    int s = 0;
    #pragma unroll
    for (int j=0;j<C;j++) s += hist[tid*C + j];
    Sc[tid] = s;
    int ws = s;
    #pragma unroll
    for (int o=16;o;o>>=1) ws += __shfl_down_sync(0xffffffffu, ws, o);
    if ((tid & 31) == 0) Sw[tid >> 5] = ws;
    __syncthreads();
    if (tid == 0){
        int cum = 0, w = 7;
        while (w > 0 && cum + Sw[w] < k){ cum += Sw[w]; w--; }
        int c = w*32 + 31;
        while (c > w*32 && cum + Sc[c] < k){ cum += Sc[c]; c--; }
        int b = c*C + C-1;
        while (b > c*C && cum + hist[b] < k){ cum += hist[b]; b--; }
        *oP = b; *oR = k - cum;
    }
    __syncthreads();
}

// ---------------- main pass: grid 550 x 256, exact cover ----------------
__global__ void __launch_bounds__(256) k_main(
    const float* __restrict__ rm,  const float* __restrict__ psm,
    const float* __restrict__ pos, const float* __restrict__ neg,
    const float* __restrict__ tgt)
{
    __shared__ double sD[8];
    int tid = threadIdx.x;
    int g = blockIdx.x*256 + tid;            // 0..NPOS-1, exact
    int b = g / HW, p = g - b*HW;

    const float2* pp2 = (const float2*)(pos + (size_t)g*FA);
    const float2* nn2 = (const float2*)(neg + (size_t)g*FA);
    float pv[FA], nv[FA];
    #pragma unroll
    for (int i=0;i<5;i++){
        float2 a = pp2[i]; pv[2*i]=a.x; pv[2*i+1]=a.y;
        float2 c = nn2[i]; nv[2*i]=c.x; nv[2*i+1]=c.y;
    }
    float x[FA];
    #pragma unroll
    for (int a=0;a<FA;a++) x[a] = psm[((size_t)(b*FA + a))*HW + p];

    double l_cp = 0.0, l_hb = 0.0;
    #pragma unroll
    for (int a=0;a<FA;a++){
        bool nz = (nv[a] != 0.0f);
        if (nz)
            atomicAdd(&g_hist[((b*NF + (a>>1)) << 12) + (int)(kmap(x[a]) >> 20)], 1);
        if (pv[a] != 0.0f){
            atomicAdd(&g_pcnt[b*NF + (a>>1)], 1);
            float pp = 1.0f/(1.0f + expf(-x[a]));
            l_cp -= (double)logf(pp + EPSV);
            const float* tp = tgt + ((size_t)g*(FA*7) + a*7);
            const float* rp = rm  + ((size_t)(b*FA*7) + a*7)*HW + p;
            #pragma unroll
            for (int j=0;j<7;j++){
                float d = fabsf(rp[(size_t)j*HW] - tp[j]);
                l_hb += (d < 1.0f) ? (double)(0.5f*d*d) : (double)(d - 0.5f);
            }
        }
        x[a] = nz ? x[a] : __int_as_float(0x7FC00000);   // NaN = masked
    }
    #pragma unroll
    for (int f=0; f<NF; f++){
        float2 w2; w2.x = x[2*f]; w2.y = x[2*f+1];
        *(float2*)(g_vbuf + ((size_t)(b*NF+f))*NPF + (size_t)p*2) = w2;
    }

    // block-reduce the two double sums (skip global atomic if zero)
    int lane = tid & 31, wd = tid >> 5;
    double r1 = wredd(l_cp);
    if (lane==0) sD[wd] = r1;
    __syncthreads();
    if (wd==0){
        double a = (lane<8)? sD[lane] : 0.0;
        a = wredd(a);
        if (lane==0 && a != 0.0) atomicAdd(&g_clspos, a);
    }
    __syncthreads();
    double r2 = wredd(l_hb);
    if (lane==0) sD[wd] = r2;
    __syncthreads();
    if (wd==0){
        double a = (lane<8)? sD[lane] : 0.0;
        a = wredd(a);
        if (lane==0 && a != 0.0) atomicAdd(&g_huber, a);
    }
}

// ------- fused select: grid (SBLK, NFR) x 256; per-frame last-block refine -------
__global__ void __launch_bounds__(256) k_sumfin(float* __restrict__ out){
    __shared__ int hist[NBIN];
    __shared__ int Sc[256];
    __shared__ int Sw[8];
    __shared__ float cand2[256];
    __shared__ double sD[8];
    __shared__ int sP, sR, s_m, s_cgt, s_last, s_gl;
    __shared__ unsigned s_tk;

    int f = blockIdx.y, tid = threadIdx.x;
    int lane = tid & 31, wd = tid >> 5;

    // every block computes the frame threshold itself (hist complete: kernel boundary)
    for (int i=tid; i<NBIN/4; i+=256){
        int4 h = ((const int4*)(g_hist + (f<<12)))[i];
        hist[4*i]=h.x; hist[4*i+1]=h.y; hist[4*i+2]=h.z; hist[4*i+3]=h.w;
    }
    __syncthreads();
    int k = 3*(g_pcnt[f] + 1);                 // floor(3*(cnt+1)) exactly
    scan_pick256(hist, Sc, Sw, k, &sP, &sR, tid);
    int P = sP, R = sR;

    // plane pass chunk: sum v(x) above-bin, stash in-bin candidates
    double acc = 0.0;
    int i = blockIdx.x*256 + tid;
    if (i < NPF/4){
        float4 q = ((const float4*)(g_vbuf + (size_t)f*NPF))[i];
        float xv[4] = {q.x, q.y, q.z, q.w};
        #pragma unroll
        for (int j=0;j<4;j++){
            float x = xv[j];
            if (x == x){                        // not NaN => neg==1 anchor
                int t = (int)(kmap(x) >> 20);
                if (t > P) acc += (double)vneg(x);
                else if (t == P){
                    int id = atomicAdd(&g_ccount[f], 1);
                    if (id < CAP) g_cbuf[f*CAP + id] = x;
                }
            }
        }
    }
    {   // block-reduce acc -> g_num, then per-frame arrival
        double r = wredd(acc);
        if (lane==0) sD[wd] = r;
        __syncthreads();
        if (wd==0){
            double a = (lane<8)? sD[lane] : 0.0;
            a = wredd(a);
            if (lane==0){
                if (a != 0.0) atomicAdd(&g_num, a);
                __threadfence();
                int old = atomicAdd(&g_fdone[f], 1);
                s_last = (old == SBLK-1);
            }
        }
    }
    __syncthreads();
    if (!s_last) return;                        // 68 of 69 blocks exit here
    __threadfence();                            // acquire all frame writes

    // ---- last block of frame f: level-2 refinement ----
    int n = *((volatile int*)&g_ccount[f]); if (n > CAP) n = CAP;
    for (int j=tid; j<NBIN; j+=256) hist[j] = 0;
    if (tid == 0){ s_m = 0; s_cgt = 0; s_tk = 0u; }
    __syncthreads();
    for (int j=tid; j<n; j+=256)
        atomicAdd(&hist[(kmap(g_cbuf[f*CAP + j]) >> 8) & 0xFFF], 1);
    __syncthreads();
    scan_pick256(hist, Sc, Sw, R, &sP, &sR, tid);
    int P2 = sP, r2 = sR;

    double acc2 = 0.0;
    for (int j=tid; j<n; j+=256){
        float x = g_cbuf[f*CAP + j];
        int t = (int)((kmap(x) >> 8) & 0xFFF);
        if (t > P2) acc2 += (double)vneg(x);
        else if (t == P2){
            int id = atomicAdd(&s_m, 1);
            if (id < 256) cand2[id] = x;
        }
    }
    __syncthreads();
    int m = s_m; if (m > 256) m = 256;
    if (m > 0){
        // exact tie-aware finish on tiny candidate set
        for (int j=tid; j<m; j+=256){
            unsigned ki = kmap(cand2[j]);
            int cgt = 0, ceq = 0;
            for (int q=0;q<m;q++){
                unsigned kq = kmap(cand2[q]);
                cgt += (kq > ki); ceq += (kq == ki);
            }
            if (cgt < r2 && r2 <= cgt + ceq) s_tk = ki;   // benign same-value race
        }
        __syncthreads();
        unsigned tk = s_tk;
        int cl = 0;
        for (int j=tid; j<m; j+=256){
            unsigned ki = kmap(cand2[j]);
            if (ki > tk){ acc2 += (double)vneg(cand2[j]); cl++; }
        }
        if (cl) atomicAdd(&s_cgt, cl);
        __syncthreads();
        if (tid == 0) acc2 += (double)(r2 - s_cgt) * (double)vneg(kunmap(tk));
    }

    // self-clean this frame's state for next invocation
    for (int j=tid; j<NBIN/4; j+=256)
        ((int4*)(g_hist + (f<<12)))[j] = make_int4(0,0,0,0);
    if (tid == 0){ g_ccount[f] = 0; g_fdone[f] = 0; }

    // block-reduce acc2 -> g_num, then global last-frame finalize
    {
        double r = wredd(acc2);
        if (lane==0) sD[wd] = r;
        __syncthreads();
        if (wd==0){
            double a = (lane<8)? sD[lane] : 0.0;
            a = wredd(a);
            if (lane==0){
                if (a != 0.0) atomicAdd(&g_num, a);
                __threadfence();
                int old = atomicAdd(&g_fin_done, 1);
                s_gl = (old == NFR-1);
            }
        }
    }
    __syncthreads();
    if (s_gl && tid < 32){
        __threadfence();
        int c = (tid < NFR) ? g_pcnt[tid] : 0;
        int cnt = c, den = (tid < NFR) ? 3*(c+1) : 0;
        #pragma unroll
        for (int o=16;o;o>>=1){
            cnt += __shfl_down_sync(0xffffffffu, cnt, o);
            den += __shfl_down_sync(0xffffffffu, den, o);
        }
        if (tid == 0){
            double num  = atomicAdd(&g_num, 0.0);       // L2 reads
            double cp   = atomicAdd(&g_clspos, 0.0);
            double hb   = atomicAdd(&g_huber, 0.0);
            double ps   = (double)cnt + 1e-6;
            double clsp = 1.5 * cp / ps;                // ALPHA
            double reg  = 2.0 * hb / ps;                // GAMMA
            double clsn = 1.0 * num / ((double)den + 1e-6); // BETA
            out[0] = (float)(clsp + clsn);  // conf_loss
            out[1] = (float)reg;            // reg_loss
            out[2] = (float)clsp;           // cls_pos_loss
            out[3] = (float)clsn;           // cls_neg_loss
            // self-clean scalars for next invocation
            g_clspos = 0.0; g_huber = 0.0; g_num = 0.0; g_fin_done = 0;
        }
        if (tid < NFR) g_pcnt[tid] = 0;
    }
}

extern "C" void kernel_launch(void* const* d_in, const int* in_sizes, int n_in,
                              void* d_out, int out_size)
{
    const float* rm  = (const float*)d_in[0];
    const float* psm = (const float*)d_in[1];
    const float* pos = (const float*)d_in[2];
    const float* neg = (const float*)d_in[3];
    const float* tgt = (const float*)d_in[4];
    float* out = (float*)d_out;

    k_main<<<NPOS/256, 256>>>(rm, psm, pos, neg, tgt);
    dim3 gs(SBLK, NFR);           // 69 x 20, covers NPF/4=17600 (69*256=17664)
    k_sumfin<<<gs, 256>>>(out);
}

// round 11
// speedup vs baseline: 1.1084x; 1.1084x over previous
#include <cuda_runtime.h>
#include <math.h>

// Problem constants
#define BB 4
#define HH 200
#define WW 176
#define HW (HH*WW)         // 35200
#define FA 10
#define NF 5
#define NFR (BB*NF)        // 20 (b,frame) pairs
#define NPF (HW*2)         // 70400 elements per frame
#define NPOS (BB*HW)       // 140800 positions = 550*256 exactly
#define EPSV 1e-6f
#define NBIN 4096
#define CAP 4096
#define SBLK 69            // blocks per frame in k_sumfin (69*256 >= NPF/4=17600)

// ---- scratch (device globals; zero-initialized at load; self-cleaning) ----
__device__ float  g_vbuf[BB*NF*NPF];   // masked psm logits, 5.6MB
__device__ int    g_hist[NFR*NBIN];    // 12-bit-prefix histograms
__device__ int    g_pcnt[NFR];
__device__ float  g_cbuf[NFR*CAP];     // threshold-bin candidates
__device__ int    g_ccount[NFR];
__device__ int    g_fdone[NFR];        // per-frame arrival counters
__device__ int    g_Pv[NFR], g_Rv[NFR];
__device__ double g_clspos, g_huber, g_num;
__device__ int    g_fin_done;

// monotonic float<->uint key mapping (ascending)
__device__ __forceinline__ unsigned kmap(float x){
    unsigned u = __float_as_uint(x);
    return (u & 0x80000000u) ? ~u : (u | 0x80000000u);
}
__device__ __forceinline__ float kunmap(unsigned m){
    unsigned u = (m & 0x80000000u) ? (m & 0x7FFFFFFFu) : ~m;
    return __uint_as_float(u);
}
// neg-class loss from raw logit (monotone non-decreasing in x => top-k by x == top-k by v)
__device__ __forceinline__ float vneg(float x){
    float pp = 1.0f/(1.0f + expf(-x));
    return -logf(1.0f - pp + EPSV);
}
__device__ __forceinline__ double wredd(double v){
    #pragma unroll
    for (int o=16;o;o>>=1) v += __shfl_down_sync(0xffffffffu, v, o);
    return v;
}

// hierarchical suffix scan over shared hist[NBIN], T threads.
// thread 0 writes (*oP,*oR); all threads sync'd on exit.
template<int T>
__device__ __forceinline__ void scan_pick(int* hist, int* Sc, int* Sw,
                                          int k, int* oP, int* oR, int tid)
{
    const int C = NBIN/T;
    int s = 0;
    #pragma unroll
    for (int j=0;j<C;j++) s += hist[tid*C + j];
    Sc[tid] = s;
    int ws = s;
    #pragma unroll
    for (int o=16;o;o>>=1) ws += __shfl_down_sync(0xffffffffu, ws, o);
    if ((tid & 31) == 0) Sw[tid >> 5] = ws;
    __syncthreads();
    if (tid == 0){
        const int NW = T/32;
        int cum = 0, w = NW-1;
        while (w > 0 && cum + Sw[w] < k){ cum += Sw[w]; w--; }
        int c = w*32 + 31;
        while (c > w*32 && cum + Sc[c] < k){ cum += Sc[c]; c--; }
        int b = c*C + C-1;
        while (b > c*C && cum + hist[b] < k){ cum += hist[b]; b--; }
        *oP = b; *oR = k - cum;
    }
    __syncthreads();
}

// ---------------- main pass: grid 550 x 256, exact cover ----------------
__global__ void __launch_bounds__(256) k_main(
    const float* __restrict__ rm,  const float* __restrict__ psm,
    const float* __restrict__ pos, const float* __restrict__ neg,
    const float* __restrict__ tgt)
{
    __shared__ double sD[8];
    int tid = threadIdx.x;
    int g = blockIdx.x*256 + tid;            // 0..NPOS-1, exact
    int b = g / HW, p = g - b*HW;

    const float2* pp2 = (const float2*)(pos + (size_t)g*FA);
    const float2* nn2 = (const float2*)(neg + (size_t)g*FA);
    float pv[FA], nv[FA];
    #pragma unroll
    for (int i=0;i<5;i++){
        float2 a = pp2[i]; pv[2*i]=a.x; pv[2*i+1]=a.y;
        float2 c = nn2[i]; nv[2*i]=c.x; nv[2*i+1]=c.y;
    }
    float x[FA];
    #pragma unroll
    for (int a=0;a<FA;a++) x[a] = psm[((size_t)(b*FA + a))*HW + p];

    double l_cp = 0.0, l_hb = 0.0;
    #pragma unroll
    for (int a=0;a<FA;a++){
        bool nz = (nv[a] != 0.0f);
        if (nz)
            atomicAdd(&g_hist[((b*NF + (a>>1)) << 12) + (int)(kmap(x[a]) >> 20)], 1);
        if (pv[a] != 0.0f){
            atomicAdd(&g_pcnt[b*NF + (a>>1)], 1);
            float pp = 1.0f/(1.0f + expf(-x[a]));
            l_cp -= (double)logf(pp + EPSV);
            const float* tp = tgt + ((size_t)g*(FA*7) + a*7);
            const float* rp = rm  + ((size_t)(b*FA*7) + a*7)*HW + p;
            #pragma unroll
            for (int j=0;j<7;j++){
                float d = fabsf(rp[(size_t)j*HW] - tp[j]);
                l_hb += (d < 1.0f) ? (double)(0.5f*d*d) : (double)(d - 0.5f);
            }
        }
        x[a] = nz ? x[a] : __int_as_float(0x7FC00000);   // NaN = masked
    }
    #pragma unroll
    for (int f=0; f<NF; f++){
        float2 w2; w2.x = x[2*f]; w2.y = x[2*f+1];
        *(float2*)(g_vbuf + ((size_t)(b*NF+f))*NPF + (size_t)p*2) = w2;
    }

    // block-reduce the two double sums (skip global atomic if zero)
    int lane = tid & 31, wd = tid >> 5;
    double r1 = wredd(l_cp);
    if (lane==0) sD[wd] = r1;
    __syncthreads();
    if (wd==0){
        double a = (lane<8)? sD[lane] : 0.0;
        a = wredd(a);
        if (lane==0 && a != 0.0) atomicAdd(&g_clspos, a);
    }
    __syncthreads();
    double r2 = wredd(l_hb);
    if (lane==0) sD[wd] = r2;
    __syncthreads();
    if (wd==0){
        double a = (lane<8)? sD[lane] : 0.0;
        a = wredd(a);
        if (lane==0 && a != 0.0) atomicAdd(&g_huber, a);
    }
}

// ---------------- per-frame threshold pick: 20 x 512 ----------------
__global__ void __launch_bounds__(512) k_scan(){
    __shared__ int hist[NBIN];
    __shared__ int Sc[512];
    __shared__ int Sw[16];
    __shared__ int sP, sR;
    int f = blockIdx.x, tid = threadIdx.x;
    for (int i=tid; i<NBIN/4; i+=512){
        int4 h = ((const int4*)(g_hist + (f<<12)))[i];
        hist[4*i]=h.x; hist[4*i+1]=h.y; hist[4*i+2]=h.z; hist[4*i+3]=h.w;
        ((int4*)(g_hist + (f<<12)))[i] = make_int4(0,0,0,0);   // self-clean
    }
    __syncthreads();
    int k = 3*(g_pcnt[f] + 1);                // floor(3*(cnt+1)) exactly
    scan_pick<512>(hist, Sc, Sw, k, &sP, &sR, tid);
    if (tid == 0){ g_Pv[f] = sP; g_Rv[f] = sR; }
}

// ------- fused plane pass + per-frame last-block refine: grid (SBLK,NFR) x 256 -------
__global__ void __launch_bounds__(256) k_sumfin(float* __restrict__ out){
    __shared__ int hist[NBIN];                // used only by last block of frame
    __shared__ int Sc[256];
    __shared__ int Sw[8];
    __shared__ float cand2[256];
    __shared__ double sD[8];
    __shared__ int sP, sR, s_m, s_cgt, s_last, s_gl;
    __shared__ unsigned s_tk;

    int f = blockIdx.y, tid = threadIdx.x;
    int lane = tid & 31, wd = tid >> 5;
    int P = g_Pv[f];                          // precomputed by k_scan (cheap L2 load)

    // plane pass chunk: sum v(x) above-bin, stash in-bin candidates
    double acc = 0.0;
    int i = blockIdx.x*256 + tid;
    if (i < NPF/4){
        float4 q = ((const float4*)(g_vbuf + (size_t)f*NPF))[i];
        float xv[4] = {q.x, q.y, q.z, q.w};
        #pragma unroll
        for (int j=0;j<4;j++){
            float x = xv[j];
            if (x == x){                        // not NaN => neg==1 anchor
                int t = (int)(kmap(x) >> 20);
                if (t > P) acc += (double)vneg(x);
                else if (t == P){
                    int id = atomicAdd(&g_ccount[f], 1);
                    if (id < CAP) g_cbuf[f*CAP + id] = x;
                }
            }
        }
    }
    {   // block-reduce acc -> g_num, then per-frame arrival
        double r = wredd(acc);
        if (lane==0) sD[wd] = r;
        __syncthreads();
        if (wd==0){
            double a = (lane<8)? sD[lane] : 0.0;
            a = wredd(a);
            if (lane==0){
                if (a != 0.0) atomicAdd(&g_num, a);
                __threadfence();
                int old = atomicAdd(&g_fdone[f], 1);
                s_last = (old == SBLK-1);
            }
        }
    }
    __syncthreads();
    if (!s_last) return;                        // 68 of 69 blocks exit here
    __threadfence();                            // acquire all frame writes

    // ---- last block of frame f: level-2 refinement ----
    int n = *((volatile int*)&g_ccount[f]); if (n > CAP) n = CAP;
    int R = g_Rv[f];
    for (int j=tid; j<NBIN; j+=256) hist[j] = 0;
    if (tid == 0){ s_m = 0; s_cgt = 0; s_tk = 0u; g_ccount[f] = 0; g_fdone[f] = 0; }
    __syncthreads();
    for (int j=tid; j<n; j+=256)
        atomicAdd(&hist[(kmap(g_cbuf[f*CAP + j]) >> 8) & 0xFFF], 1);
    __syncthreads();
    scan_pick<256>(hist, Sc, Sw, R, &sP, &sR, tid);
    int P2 = sP, r2 = sR;

    double acc2 = 0.0;
    for (int j=tid; j<n; j+=256){
        float x = g_cbuf[f*CAP + j];
        int t = (int)((kmap(x) >> 8) & 0xFFF);
        if (t > P2) acc2 += (double)vneg(x);
        else if (t == P2){
            int id = atomicAdd(&s_m, 1);
            if (id < 256) cand2[id] = x;
        }
    }
    __syncthreads();
    int m = s_m; if (m > 256) m = 256;
    if (m > 0){
        // exact tie-aware finish on tiny candidate set
        for (int j=tid; j<m; j+=256){
            unsigned ki = kmap(cand2[j]);
            int cgt = 0, ceq = 0;
            for (int q=0;q<m;q++){
                unsigned kq = kmap(cand2[q]);
                cgt += (kq > ki); ceq += (kq == ki);
            }
            if (cgt < r2 && r2 <= cgt + ceq) s_tk = ki;   // benign same-value race
        }
        __syncthreads();
        unsigned tk = s_tk;
        int cl = 0;
        for (int j=tid; j<m; j+=256){
            unsigned ki = kmap(cand2[j]);
            if (ki > tk){ acc2 += (double)vneg(cand2[j]); cl++; }
        }
        if (cl) atomicAdd(&s_cgt, cl);
        __syncthreads();
        if (tid == 0) acc2 += (double)(r2 - s_cgt) * (double)vneg(kunmap(tk));
    }

    // block-reduce acc2 -> g_num, then global last-frame finalize
    {
        double r = wredd(acc2);
        if (lane==0) sD[wd] = r;
        __syncthreads();
        if (wd==0){
            double a = (lane<8)? sD[lane] : 0.0;
            a = wredd(a);
            if (lane==0){
                if (a != 0.0) atomicAdd(&g_num, a);
                __threadfence();
                int old = atomicAdd(&g_fin_done, 1);
                s_gl = (old == NFR-1);
            }
        }
    }
    __syncthreads();
    if (s_gl && tid < 32){
        __threadfence();
        int c = (tid < NFR) ? g_pcnt[tid] : 0;
        int cnt = c, den = (tid < NFR) ? 3*(c+1) : 0;
        #pragma unroll
        for (int o=16;o;o>>=1){
            cnt += __shfl_down_sync(0xffffffffu, cnt, o);
            den += __shfl_down_sync(0xffffffffu, den, o);
        }
        if (tid == 0){
            double num  = atomicAdd(&g_num, 0.0);       // L2 reads
            double cp   = atomicAdd(&g_clspos, 0.0);
            double hb   = atomicAdd(&g_huber, 0.0);
            double ps   = (double)cnt + 1e-6;
            double clsp = 1.5 * cp / ps;                // ALPHA
            double reg  = 2.0 * hb / ps;                // GAMMA
            double clsn = 1.0 * num / ((double)den + 1e-6); // BETA
            out[0] = (float)(clsp + clsn);  // conf_loss
            out[1] = (float)reg;            // reg_loss
            out[2] = (float)clsp;           // cls_pos_loss
            out[3] = (float)clsn;           // cls_neg_loss
            // self-clean scalars for next invocation
            g_clspos = 0.0; g_huber = 0.0; g_num = 0.0; g_fin_done = 0;
        }
        if (tid < NFR) g_pcnt[tid] = 0;
    }
}

extern "C" void kernel_launch(void* const* d_in, const int* in_sizes, int n_in,
                              void* d_out, int out_size)
{
    const float* rm  = (const float*)d_in[0];
    const float* psm = (const float*)d_in[1];
    const float* pos = (const float*)d_in[2];
    const float* neg = (const float*)d_in[3];
    const float* tgt = (const float*)d_in[4];
    float* out = (float*)d_out;

    k_main<<<NPOS/256, 256>>>(rm, psm, pos, neg, tgt);
    k_scan<<<NFR, 512>>>();
    dim3 gs(SBLK, NFR);            // 69 x 20
    k_sumfin<<<gs, 256>>>(out);
}